// round 1
// baseline (speedup 1.0000x reference)
#include <cuda_runtime.h>

#define N_NODES 50000
#define N_EDGES 600000
#define D_IN    2050
#define D_H     128

// ---------------- scratch (device globals; no allocation allowed) ----------
__device__ float g_deg[N_NODES];
__device__ float g_dinv[N_NODES];
__device__ float g_self[N_NODES];          // dinv^2 (self-loop norm)
__device__ float g_norm[N_EDGES];
__device__ float g_t[(size_t)N_NODES * D_H];   // GEMM output (pre-aggregation)
__device__ float g_h[(size_t)N_NODES * D_H];   // aggregated output / next input
__device__ int   g_is64;                   // 1 if edge_index is int64, 0 if int32

// ---------------- helpers ---------------------------------------------------
__device__ __forceinline__ int load_idx(const void* p, long i, int is64) {
    if (is64) return (int)((const long long*)p)[i];
    return ((const int*)p)[i];
}

__device__ __forceinline__ void red_add_v4(float* addr, float a, float b, float c, float d) {
    asm volatile("red.global.add.v4.f32 [%0], {%1,%2,%3,%4};"
                 :: "l"(addr), "f"(a), "f"(b), "f"(c), "f"(d) : "memory");
}

// ---------------- dtype detection ------------------------------------------
// Random indices in [0,50000): if data were int32, odd 32-bit words being all
// zero over 64 samples has probability ~0. If int64 (values < 2^31), the high
// words are exactly 0.
__global__ void k_detect(const int* __restrict__ ei) {
    if (threadIdx.x == 0 && blockIdx.x == 0) {
        int is64 = 1;
        for (int i = 0; i < 64; i++) {
            if (ei[2 * i + 1] != 0) { is64 = 0; break; }
        }
        g_is64 = is64;
    }
}

// ---------------- normalization precompute ---------------------------------
__global__ void k_deg_init() {
    int i = blockIdx.x * blockDim.x + threadIdx.x;
    if (i < N_NODES) g_deg[i] = 1.0f;   // self-loop weight
}

__global__ void k_deg_acc(const void* __restrict__ ei, const float* __restrict__ w) {
    int e = blockIdx.x * blockDim.x + threadIdx.x;
    if (e >= N_EDGES) return;
    int is64 = g_is64;
    int d = load_idx(ei, (long)N_EDGES + e, is64);   // dst row of edge_index
    atomicAdd(&g_deg[d], w[e]);
}

__global__ void k_dinv() {
    int i = blockIdx.x * blockDim.x + threadIdx.x;
    if (i >= N_NODES) return;
    float d = g_deg[i];                 // >= 1 always (self loop)
    float r = rsqrtf(d);
    g_dinv[i] = r;
    g_self[i] = r * r;
}

__global__ void k_norm(const void* __restrict__ ei, const float* __restrict__ w) {
    int e = blockIdx.x * blockDim.x + threadIdx.x;
    if (e >= N_EDGES) return;
    int is64 = g_is64;
    int s = load_idx(ei, e, is64);
    int d = load_idx(ei, (long)N_EDGES + e, is64);
    g_norm[e] = w[e] * g_dinv[s] * g_dinv[d];
}

// ---------------- tiled fp32 GEMM:  g_t = A @ W  (N = 128 fixed) -----------
// BM=64, BN=128, BK=32, 256 threads, each computes a 4x8 micro-tile.
#define BM 64
#define BN 128
#define BK 32
#define TM 4
#define TN 8

template <bool FROM_H>   // FROM_H: A = relu(g_h), K = D_H; else A = x, K = D_IN
__global__ void k_gemm(const float* __restrict__ A_ext,
                       const float* __restrict__ W, int K) {
    __shared__ float As[BK][BM + 1];
    __shared__ float Bs[BK][BN];

    const float* A = FROM_H ? g_h : A_ext;

    int block_row = blockIdx.x * BM;
    int tid = threadIdx.x;
    int tx = tid & 15;   // 16 column groups (8 cols each)
    int ty = tid >> 4;   // 16 row groups (4 rows each)

    float acc[TM][TN];
    #pragma unroll
    for (int i = 0; i < TM; i++)
        #pragma unroll
        for (int j = 0; j < TN; j++) acc[i][j] = 0.0f;

    for (int k0 = 0; k0 < K; k0 += BK) {
        // Load A tile: BM x BK (2048 elems, 8 per thread, kk fastest = coalesced)
        #pragma unroll
        for (int i = 0; i < 8; i++) {
            int idx = tid + i * 256;
            int kk = idx & 31;
            int m  = idx >> 5;
            int grow = block_row + m;
            int gk   = k0 + kk;
            float v = 0.0f;
            if (grow < N_NODES && gk < K) {
                v = A[(long)grow * K + gk];
                if (FROM_H) v = fmaxf(v, 0.0f);
            }
            As[kk][m] = v;
        }
        // Load B tile: BK x BN via float4 (1024 float4s, 4 per thread)
        #pragma unroll
        for (int i = 0; i < 4; i++) {
            int idx = tid + i * 256;
            int n4  = idx & 31;     // 32 float4s per row
            int kk  = idx >> 5;
            float4 v = make_float4(0.f, 0.f, 0.f, 0.f);
            int gk = k0 + kk;
            if (gk < K) v = *(const float4*)&W[(long)gk * BN + n4 * 4];
            *(float4*)&Bs[kk][n4 * 4] = v;
        }
        __syncthreads();

        #pragma unroll
        for (int kk = 0; kk < BK; kk++) {
            float a[TM], b[TN];
            #pragma unroll
            for (int i = 0; i < TM; i++) a[i] = As[kk][ty * TM + i];
            #pragma unroll
            for (int j = 0; j < TN; j++) b[j] = Bs[kk][tx * TN + j];
            #pragma unroll
            for (int i = 0; i < TM; i++)
                #pragma unroll
                for (int j = 0; j < TN; j++)
                    acc[i][j] = fmaf(a[i], b[j], acc[i][j]);
        }
        __syncthreads();
    }

    #pragma unroll
    for (int i = 0; i < TM; i++) {
        int grow = block_row + ty * TM + i;
        if (grow < N_NODES) {
            #pragma unroll
            for (int j = 0; j < TN; j += 4) {
                *(float4*)&g_t[(long)grow * D_H + tx * TN + j] =
                    make_float4(acc[i][j], acc[i][j + 1], acc[i][j + 2], acc[i][j + 3]);
            }
        }
    }
}

// ---------------- per-layer init: g_h = g_t * selfnorm + bias ---------------
__global__ void k_init_agg(const float* __restrict__ bias) {
    int i = blockIdx.x * blockDim.x + threadIdx.x;   // N_NODES * 32 threads
    if (i >= N_NODES * 32) return;
    int row = i >> 5;
    int c   = i & 31;
    float sn = g_self[row];
    float4 v  = ((const float4*)(g_t + (size_t)row * D_H))[c];
    float4 bb = ((const float4*)bias)[c];
    ((float4*)(g_h + (size_t)row * D_H))[c] =
        make_float4(fmaf(v.x, sn, bb.x), fmaf(v.y, sn, bb.y),
                    fmaf(v.z, sn, bb.z), fmaf(v.w, sn, bb.w));
}

// ---------------- edge scatter: g_h[dst] += g_t[src] * norm -----------------
// One warp per edge; each lane handles one float4 (128 floats / 32 lanes).
__global__ void k_scatter(const void* __restrict__ ei) {
    int gw   = (blockIdx.x * blockDim.x + threadIdx.x) >> 5;
    int lane = threadIdx.x & 31;
    if (gw >= N_EDGES) return;
    int is64 = g_is64;
    int s = load_idx(ei, gw, is64);
    int d = load_idx(ei, (long)N_EDGES + gw, is64);
    float nv = g_norm[gw];
    float4 v = ((const float4*)(g_t + (size_t)s * D_H))[lane];
    float* out = g_h + (size_t)d * D_H + lane * 4;
    red_add_v4(out, v.x * nv, v.y * nv, v.z * nv, v.w * nv);
}

// ---------------- log_softmax (one warp per row) ----------------------------
__global__ void k_logsoftmax(float* __restrict__ out) {
    int row  = (blockIdx.x * blockDim.x + threadIdx.x) >> 5;
    int lane = threadIdx.x & 31;
    if (row >= N_NODES) return;
    float4 v = ((const float4*)(g_h + (size_t)row * D_H))[lane];
    float m = fmaxf(fmaxf(v.x, v.y), fmaxf(v.z, v.w));
    #pragma unroll
    for (int o = 16; o; o >>= 1) m = fmaxf(m, __shfl_xor_sync(0xFFFFFFFFu, m, o));
    float s = expf(v.x - m) + expf(v.y - m) + expf(v.z - m) + expf(v.w - m);
    #pragma unroll
    for (int o = 16; o; o >>= 1) s += __shfl_xor_sync(0xFFFFFFFFu, s, o);
    float ls = m + logf(s);
    ((float4*)(out + (size_t)row * D_H))[lane] =
        make_float4(v.x - ls, v.y - ls, v.z - ls, v.w - ls);
}

// ---------------- launch ----------------------------------------------------
extern "C" void kernel_launch(void* const* d_in, const int* in_sizes, int n_in,
                              void* d_out, int out_size) {
    const float* x  = (const float*)d_in[0];
    const void*  ei = d_in[1];                 // int64 or int32, detected at runtime
    const float* ea = (const float*)d_in[2];
    const float* W1 = (const float*)d_in[3];
    const float* b1 = (const float*)d_in[4];
    const float* W2 = (const float*)d_in[5];
    const float* b2 = (const float*)d_in[6];
    const float* W3 = (const float*)d_in[7];
    const float* b3 = (const float*)d_in[8];
    const float* W4 = (const float*)d_in[9];
    const float* b4 = (const float*)d_in[10];
    float* out = (float*)d_out;

    const int TB = 256;
    const int GB_N    = (N_NODES + TB - 1) / TB;          // 196
    const int GB_E    = (N_EDGES + TB - 1) / TB;          // 2344
    const int GB_GEMM = (N_NODES + BM - 1) / BM;          // 782
    const int GB_ROWS = (N_NODES * 32 + TB - 1) / TB;     // 6250
    const int GB_SCAT = (N_EDGES * 32) / TB;              // 75000

    // normalization (once per launch, deterministic)
    k_detect<<<1, 32>>>((const int*)ei);
    k_deg_init<<<GB_N, TB>>>();
    k_deg_acc<<<GB_E, TB>>>(ei, ea);
    k_dinv<<<GB_N, TB>>>();
    k_norm<<<GB_E, TB>>>(ei, ea);

    // layer 1 (input = x, K = 2050)
    k_gemm<false><<<GB_GEMM, TB>>>(x, W1, D_IN);
    k_init_agg<<<GB_ROWS, TB>>>(b1);
    k_scatter<<<GB_SCAT, TB>>>(ei);

    // layer 2
    k_gemm<true><<<GB_GEMM, TB>>>(nullptr, W2, D_H);
    k_init_agg<<<GB_ROWS, TB>>>(b2);
    k_scatter<<<GB_SCAT, TB>>>(ei);

    // layer 3
    k_gemm<true><<<GB_GEMM, TB>>>(nullptr, W3, D_H);
    k_init_agg<<<GB_ROWS, TB>>>(b3);
    k_scatter<<<GB_SCAT, TB>>>(ei);

    // layer 4
    k_gemm<true><<<GB_GEMM, TB>>>(nullptr, W4, D_H);
    k_init_agg<<<GB_ROWS, TB>>>(b4);
    k_scatter<<<GB_SCAT, TB>>>(ei);

    // output
    k_logsoftmax<<<GB_ROWS, TB>>>(out);
}